// round 10
// baseline (speedup 1.0000x reference)
#include <cuda_runtime.h>
#include <cstdint>

// Problem constants (fixed by the dataset instance).
#define BB 512
#define LL 512
#define CC 256
#define NTH 256
#define CSL 8                 // channel slices per batch (32 ch = 8 float4 each)
#define C4S 8                 // float4 per slice
#define LGR 32                // l-groups (tid >> 3)
#define RITER (LL / LGR)      // 16 read iters per tile
#define TILES (BB * CSL)      // 4096
#define GRID 512
#define TPB (TILES / GRID)    // 8 tiles per block
#define C4FULL (CC / 4)       // 64 float4 per full row
#define NWARP (NTH / 32)      // 8

// Least-squares constants for t = 0..511:
//   sum_t = 130816, sum_t2 = 44608256, denom = sum_t2 - sum_t^2/n = 11184768
#define SUM_T     130816.0f
#define K1        255.5f
#define INV_DENOM (1.0f / 11184768.0f)
#define INV_N     (1.0f / 512.0f)

__device__ __forceinline__ void f4add(float4& a, const float4 b) {
    a.x += b.x; a.y += b.y; a.z += b.z; a.w += b.w;
}

__device__ __forceinline__ void f4shfl_add(float4& a, int mask) {
    a.x += __shfl_xor_sync(0xffffffffu, a.x, mask);
    a.y += __shfl_xor_sync(0xffffffffu, a.y, mask);
    a.z += __shfl_xor_sync(0xffffffffu, a.z, mask);
    a.w += __shfl_xor_sync(0xffffffffu, a.w, mask);
}

__global__ __launch_bounds__(NTH)
void lr_forecast_d8(const float* __restrict__ x,
                    float* __restrict__ out,
                    int t_out_len)
{
    const int g    = blockIdx.x;
    const int tid  = threadIdx.x;
    const int c4   = tid & (C4S - 1);  // 0..7 (float4 column in slice)
    const int lg   = tid >> 3;         // 0..31 (l-stride group)
    const int warp = tid >> 5;         // 0..7
    const int lane = tid & 31;

    __shared__ float4 s_psy [NWARP][C4S];
    __shared__ float4 s_psty[NWARP][C4S];
    __shared__ float4 s_sl[C4S];
    __shared__ float4 s_ic[C4S];

    // ---- monolithic read phase (front-batched 8-deep LDG.128) ----
    auto read_tile = [&](int tile, float4& sl_o, float4& ic_o) {
        const int b  = tile >> 3;
        const int cs = tile & (CSL - 1);
        const float4* xb = reinterpret_cast<const float4*>(
                               x + (size_t)b * LL * CC) + cs * C4S + c4;
        float4 sy  = make_float4(0.f, 0.f, 0.f, 0.f);
        float4 sty = make_float4(0.f, 0.f, 0.f, 0.f);
        #pragma unroll 8
        for (int i = 0; i < RITER; i++) {
            int l = lg + i * LGR;
            float4 v = __ldg(&xb[(size_t)l * C4FULL]);
            float tf = (float)l;
            f4add(sy, v);
            sty.x = fmaf(tf, v.x, sty.x);
            sty.y = fmaf(tf, v.y, sty.y);
            sty.z = fmaf(tf, v.z, sty.z);
            sty.w = fmaf(tf, v.w, sty.w);
        }
        // warp-level reduce: lane = lg_local*8 + c4; xor 8,16 sums the
        // 4 lg_local groups; lanes 0..7 hold warp totals for c4 0..7.
        f4shfl_add(sy, 8);  f4shfl_add(sy, 16);
        f4shfl_add(sty, 8); f4shfl_add(sty, 16);

        if (lane < C4S) {
            s_psy [warp][lane] = sy;
            s_psty[warp][lane] = sty;
        }
        __syncthreads();

        if (tid < C4S) {
            float4 Sy = s_psy[0][tid], Sty = s_psty[0][tid];
            #pragma unroll
            for (int w = 1; w < NWARP; w++) {
                f4add(Sy,  s_psy [w][tid]);
                f4add(Sty, s_psty[w][tid]);
            }
            float4 SL, IC;
            SL.x = (Sty.x - K1 * Sy.x) * INV_DENOM;
            SL.y = (Sty.y - K1 * Sy.y) * INV_DENOM;
            SL.z = (Sty.z - K1 * Sy.z) * INV_DENOM;
            SL.w = (Sty.w - K1 * Sy.w) * INV_DENOM;
            IC.x = (Sy.x - SL.x * SUM_T) * INV_N;
            IC.y = (Sy.y - SL.y * SUM_T) * INV_N;
            IC.z = (Sy.z - SL.z * SUM_T) * INV_N;
            IC.w = (Sy.w - SL.w * SUM_T) * INV_N;
            s_sl[tid] = SL;
            s_ic[tid] = IC;
        }
        __syncthreads();
        sl_o = s_sl[c4];
        ic_o = s_ic[c4];
    };

    // ---- monolithic write phase ----
    auto write_tile = [&](int tile, float4 sl, float4 ic) {
        const int b  = tile >> 3;
        const int cs = tile & (CSL - 1);
        float4* ob = reinterpret_cast<float4*>(
                         out + (size_t)b * t_out_len * CC) + cs * C4S + c4;
        #pragma unroll 8
        for (int t = lg; t < t_out_len; t += LGR) {   // 19 iters
            float tf = (float)t;
            float4 o;
            o.x = fmaf(sl.x, tf, ic.x);
            o.y = fmaf(sl.y, tf, ic.y);
            o.z = fmaf(sl.z, tf, ic.z);
            o.w = fmaf(sl.w, tf, ic.w);
            ob[(size_t)t * C4FULL] = o;
        }
    };

    float4 sl0, ic0, sl1, ic1;

    if ((g & 1) == 0) {
        // Even blocks: R0 W0 R1 W1 ... R7 W7
        #pragma unroll
        for (int s = 0; s < TPB; s++) {
            int tile = g + s * GRID;
            read_tile(tile, sl0, ic0);
            write_tile(tile, sl0, ic0);
        }
    } else {
        // Odd blocks (depth-2 pipeline): R0 R1 W0 R2 W1 ... R7 W6 W7
        read_tile(g, sl0, ic0);
        #pragma unroll
        for (int s = 1; s < TPB; s++) {
            read_tile(g + s * GRID, sl1, ic1);
            write_tile(g + (s - 1) * GRID, sl0, ic0);
            sl0 = sl1; ic0 = ic1;
        }
        write_tile(g + (TPB - 1) * GRID, sl0, ic0);
    }
}

extern "C" void kernel_launch(void* const* d_in, const int* in_sizes, int n_in,
                              void* d_out, int out_size)
{
    const float* x = (const float*)d_in[0];
    float* out = (float*)d_out;
    int t_out_len = out_size / (BB * CC);   // 608 for pred_len = 96

    lr_forecast_d8<<<GRID, NTH>>>(x, out, t_out_len);
}

// round 11
// speedup vs baseline: 1.0285x; 1.0285x over previous
#include <cuda_runtime.h>
#include <cstdint>

// Problem constants (fixed by the dataset instance).
#define BB 512
#define LL 512
#define CC 256
#define NTH 256
#define CSL 8                 // channel slices per batch (32 ch = 8 float4 each)
#define C4S 8                 // float4 per slice
#define LGR 32                // l-groups (tid >> 3)
#define RITER (LL / LGR)      // 16 read iters per tile
#define TILES (BB * CSL)      // 4096
#define GRID 1024
#define TPB (TILES / GRID)    // 4 tiles per block
#define C4FULL (CC / 4)       // 64 float4 per full row
#define NWARP (NTH / 32)      // 8

// Least-squares constants for t = 0..511:
//   sum_t = 130816, sum_t2 = 44608256, denom = sum_t2 - sum_t^2/n = 11184768
#define SUM_T     130816.0f
#define K1        255.5f
#define INV_DENOM (1.0f / 11184768.0f)
#define INV_N     (1.0f / 512.0f)

__device__ __forceinline__ void f4add(float4& a, const float4 b) {
    a.x += b.x; a.y += b.y; a.z += b.z; a.w += b.w;
}

__device__ __forceinline__ void f4shfl_add(float4& a, int mask) {
    a.x += __shfl_xor_sync(0xffffffffu, a.x, mask);
    a.y += __shfl_xor_sync(0xffffffffu, a.y, mask);
    a.z += __shfl_xor_sync(0xffffffffu, a.z, mask);
    a.w += __shfl_xor_sync(0xffffffffu, a.w, mask);
}

__global__ __launch_bounds__(NTH)
void lr_forecast_r11(const float* __restrict__ x,
                     float* __restrict__ out,
                     int t_out_len)
{
    const int g    = blockIdx.x;
    const int tid  = threadIdx.x;
    const int c4   = tid & (C4S - 1);  // 0..7 (float4 column in slice)
    const int lg   = tid >> 3;         // 0..31 (l-stride group)
    const int warp = tid >> 5;         // 0..7
    const int lane = tid & 31;

    __shared__ float4 s_psy [NWARP][C4S];
    __shared__ float4 s_psty[NWARP][C4S];
    __shared__ float4 s_sl[C4S];
    __shared__ float4 s_ic[C4S];

    // ---- monolithic read phase (front-batched 8-deep LDG.128) ----
    auto read_tile = [&](int tile, float4& sl_o, float4& ic_o) {
        const int b  = tile >> 3;
        const int cs = tile & (CSL - 1);
        const float4* xb = reinterpret_cast<const float4*>(
                               x + (size_t)b * LL * CC) + cs * C4S + c4;
        float4 sy  = make_float4(0.f, 0.f, 0.f, 0.f);
        float4 sty = make_float4(0.f, 0.f, 0.f, 0.f);
        #pragma unroll 8
        for (int i = 0; i < RITER; i++) {
            int l = lg + i * LGR;
            float4 v = __ldg(&xb[(size_t)l * C4FULL]);
            float tf = (float)l;
            f4add(sy, v);
            sty.x = fmaf(tf, v.x, sty.x);
            sty.y = fmaf(tf, v.y, sty.y);
            sty.z = fmaf(tf, v.z, sty.z);
            sty.w = fmaf(tf, v.w, sty.w);
        }
        // warp-level reduce: lane = lg_local*8 + c4; xor 8,16 sums the
        // 4 lg_local groups; lanes 0..7 hold warp totals for c4 0..7.
        f4shfl_add(sy, 8);  f4shfl_add(sy, 16);
        f4shfl_add(sty, 8); f4shfl_add(sty, 16);

        if (lane < C4S) {
            s_psy [warp][lane] = sy;
            s_psty[warp][lane] = sty;
        }
        __syncthreads();

        if (tid < C4S) {
            float4 Sy = s_psy[0][tid], Sty = s_psty[0][tid];
            #pragma unroll
            for (int w = 1; w < NWARP; w++) {
                f4add(Sy,  s_psy [w][tid]);
                f4add(Sty, s_psty[w][tid]);
            }
            float4 SL, IC;
            SL.x = (Sty.x - K1 * Sy.x) * INV_DENOM;
            SL.y = (Sty.y - K1 * Sy.y) * INV_DENOM;
            SL.z = (Sty.z - K1 * Sy.z) * INV_DENOM;
            SL.w = (Sty.w - K1 * Sy.w) * INV_DENOM;
            IC.x = (Sy.x - SL.x * SUM_T) * INV_N;
            IC.y = (Sy.y - SL.y * SUM_T) * INV_N;
            IC.z = (Sy.z - SL.z * SUM_T) * INV_N;
            IC.w = (Sy.w - SL.w * SUM_T) * INV_N;
            s_sl[tid] = SL;
            s_ic[tid] = IC;
        }
        __syncthreads();
        sl_o = s_sl[c4];
        ic_o = s_ic[c4];
    };

    // ---- monolithic write phase ----
    auto write_tile = [&](int tile, float4 sl, float4 ic) {
        const int b  = tile >> 3;
        const int cs = tile & (CSL - 1);
        float4* ob = reinterpret_cast<float4*>(
                         out + (size_t)b * t_out_len * CC) + cs * C4S + c4;
        #pragma unroll 8
        for (int t = lg; t < t_out_len; t += LGR) {   // 19 iters
            float tf = (float)t;
            float4 o;
            o.x = fmaf(sl.x, tf, ic.x);
            o.y = fmaf(sl.y, tf, ic.y);
            o.z = fmaf(sl.z, tf, ic.z);
            o.w = fmaf(sl.w, tf, ic.w);
            ob[(size_t)t * C4FULL] = o;
        }
    };

    float4 sl0, ic0, sl1, ic1;

    if ((g & 1) == 0) {
        // Even blocks: R0 W0 R1 W1 R2 W2 R3 W3
        #pragma unroll
        for (int s = 0; s < TPB; s++) {
            int tile = g + s * GRID;
            read_tile(tile, sl0, ic0);
            write_tile(tile, sl0, ic0);
        }
    } else {
        // Odd blocks (depth-2 pipeline): R0 R1 W0 R2 W1 R3 W2 W3
        read_tile(g, sl0, ic0);
        #pragma unroll
        for (int s = 1; s < TPB; s++) {
            read_tile(g + s * GRID, sl1, ic1);
            write_tile(g + (s - 1) * GRID, sl0, ic0);
            sl0 = sl1; ic0 = ic1;
        }
        write_tile(g + (TPB - 1) * GRID, sl0, ic0);
    }
}

extern "C" void kernel_launch(void* const* d_in, const int* in_sizes, int n_in,
                              void* d_out, int out_size)
{
    const float* x = (const float*)d_in[0];
    float* out = (float*)d_out;
    int t_out_len = out_size / (BB * CC);   // 608 for pred_len = 96

    lr_forecast_r11<<<GRID, NTH>>>(x, out, t_out_len);
}

// round 12
// speedup vs baseline: 1.0670x; 1.0375x over previous
#include <cuda_runtime.h>
#include <cstdint>

// Problem constants (fixed by the dataset instance).
#define BB 512
#define LL 512
#define CC 256
#define NTH 256
#define HTH 128               // threads per half
#define CSL 8                 // channel slices per batch (32 ch = 8 float4 each)
#define C4S 8                 // float4 per slice
#define LGR 16                // l-groups per half (ht >> 3)
#define RITER (LL / LGR)      // 32 read iters per tile
#define TILES (BB * CSL)      // 4096
#define GRID 1024             // 2 halves * 2 tiles each = 4 tiles per block
#define C4FULL (CC / 4)       // 64 float4 per full row
#define HWARPS 4              // warps per half

// Least-squares constants for t = 0..511:
//   sum_t = 130816, sum_t2 = 44608256, denom = sum_t2 - sum_t^2/n = 11184768
#define SUM_T     130816.0f
#define K1        255.5f
#define INV_DENOM (1.0f / 11184768.0f)
#define INV_N     (1.0f / 512.0f)

__device__ __forceinline__ void f4add(float4& a, const float4 b) {
    a.x += b.x; a.y += b.y; a.z += b.z; a.w += b.w;
}

__global__ __launch_bounds__(NTH)
void lr_forecast_hsplit(const float* __restrict__ x,
                        float* __restrict__ out,
                        int t_out_len)
{
    const int g    = blockIdx.x;
    const int tid  = threadIdx.x;
    const int h    = tid >> 7;          // half 0 / 1
    const int ht   = tid & (HTH - 1);   // tid within half
    const int c4   = ht & (C4S - 1);    // 0..7  float4 column
    const int lg   = ht >> 3;           // 0..15 l-stride group
    const int warp = ht >> 5;           // warp within half 0..3

    __shared__ float4 s_sy [2][LGR][C4S];
    __shared__ float4 s_sty[2][LGR][C4S];
    __shared__ float4 s_sl[2][C4S];
    __shared__ float4 s_ic[2][C4S];

    const int barid = h + 1;   // named barriers 1 and 2 (never bar 0)
    auto half_bar = [&]() {
        asm volatile("bar.sync %0, %1;" :: "r"(barid), "r"(HTH) : "memory");
    };

    // ---- monolithic read phase (front-batched 8-deep LDG.128) ----
    auto read_tile = [&](int tile, float4& sl_o, float4& ic_o) {
        const int b  = tile >> 3;
        const int cs = tile & (CSL - 1);
        const float4* xb = reinterpret_cast<const float4*>(
                               x + (size_t)b * LL * CC) + cs * C4S + c4;
        float4 sy  = make_float4(0.f, 0.f, 0.f, 0.f);
        float4 sty = make_float4(0.f, 0.f, 0.f, 0.f);
        #pragma unroll 8
        for (int i = 0; i < RITER; i++) {
            int l = lg + i * LGR;
            float4 v = __ldg(&xb[(size_t)l * C4FULL]);
            float tf = (float)l;
            f4add(sy, v);
            sty.x = fmaf(tf, v.x, sty.x);
            sty.y = fmaf(tf, v.y, sty.y);
            sty.z = fmaf(tf, v.z, sty.z);
            sty.w = fmaf(tf, v.w, sty.w);
        }
        // smem tree reduce over 16 l-groups within this half
        s_sy [h][lg][c4] = sy;
        s_sty[h][lg][c4] = sty;
        half_bar();
        if (lg < 4) {
            float4 a = s_sy[h][lg][c4];
            f4add(a, s_sy[h][lg +  4][c4]);
            f4add(a, s_sy[h][lg +  8][c4]);
            f4add(a, s_sy[h][lg + 12][c4]);
            s_sy[h][lg][c4] = a;
            float4 t = s_sty[h][lg][c4];
            f4add(t, s_sty[h][lg +  4][c4]);
            f4add(t, s_sty[h][lg +  8][c4]);
            f4add(t, s_sty[h][lg + 12][c4]);
            s_sty[h][lg][c4] = t;
        }
        half_bar();
        if (lg == 0) {
            float4 Sy = s_sy[h][0][c4], Sty = s_sty[h][0][c4];
            f4add(Sy,  s_sy [h][1][c4]); f4add(Sy,  s_sy [h][2][c4]); f4add(Sy,  s_sy [h][3][c4]);
            f4add(Sty, s_sty[h][1][c4]); f4add(Sty, s_sty[h][2][c4]); f4add(Sty, s_sty[h][3][c4]);
            float4 SL, IC;
            SL.x = (Sty.x - K1 * Sy.x) * INV_DENOM;
            SL.y = (Sty.y - K1 * Sy.y) * INV_DENOM;
            SL.z = (Sty.z - K1 * Sy.z) * INV_DENOM;
            SL.w = (Sty.w - K1 * Sy.w) * INV_DENOM;
            IC.x = (Sy.x - SL.x * SUM_T) * INV_N;
            IC.y = (Sy.y - SL.y * SUM_T) * INV_N;
            IC.z = (Sy.z - SL.z * SUM_T) * INV_N;
            IC.w = (Sy.w - SL.w * SUM_T) * INV_N;
            s_sl[h][c4] = SL;
            s_ic[h][c4] = IC;
        }
        half_bar();
        sl_o = s_sl[h][c4];
        ic_o = s_ic[h][c4];
        half_bar();   // protect smem for the next read_tile
    };

    // ---- monolithic write phase ----
    auto write_tile = [&](int tile, float4 sl, float4 ic) {
        const int b  = tile >> 3;
        const int cs = tile & (CSL - 1);
        float4* ob = reinterpret_cast<float4*>(
                         out + (size_t)b * t_out_len * CC) + cs * C4S + c4;
        #pragma unroll 8
        for (int t = lg; t < t_out_len; t += LGR) {   // 38 iters
            float tf = (float)t;
            float4 o;
            o.x = fmaf(sl.x, tf, ic.x);
            o.y = fmaf(sl.y, tf, ic.y);
            o.z = fmaf(sl.z, tf, ic.z);
            o.w = fmaf(sl.w, tf, ic.w);
            ob[(size_t)t * C4FULL] = o;
        }
    };

    // tiles for this half: T0 = g + (2h)*GRID, T1 = g + (2h+1)*GRID
    const int t0 = g + (2 * h) * GRID;
    const int t1 = g + (2 * h + 1) * GRID;

    float4 sl0, ic0, sl1, ic1;

    if (h == 0) {
        // Half 0: R0 W0 R1 W1
        read_tile(t0, sl0, ic0);
        write_tile(t0, sl0, ic0);
        read_tile(t1, sl1, ic1);
        write_tile(t1, sl1, ic1);
    } else {
        // Half 1 (depth-2 pipeline): R0 R1 W0 W1
        // -> while half 0 writes, half 1 reads, and vice versa.
        read_tile(t0, sl0, ic0);
        read_tile(t1, sl1, ic1);
        write_tile(t0, sl0, ic0);
        write_tile(t1, sl1, ic1);
    }
}

extern "C" void kernel_launch(void* const* d_in, const int* in_sizes, int n_in,
                              void* d_out, int out_size)
{
    const float* x = (const float*)d_in[0];
    float* out = (float*)d_out;
    int t_out_len = out_size / (BB * CC);   // 608 for pred_len = 96

    lr_forecast_hsplit<<<GRID, NTH>>>(x, out, t_out_len);
}

// round 13
// speedup vs baseline: 1.0798x; 1.0120x over previous
#include <cuda_runtime.h>
#include <cstdint>

// Problem constants (fixed by the dataset instance).
#define BB 512
#define LL 512
#define CC 256
#define NTH 256
#define HTH 128               // threads per half
#define CSL 8                 // channel slices per batch (32 ch = 8 float4 each)
#define C4S 8                 // float4 per slice
#define LGR 16                // l-groups per half (ht >> 3)
#define RITER (LL / LGR)      // 32 read iters per tile
#define TILES (BB * CSL)      // 4096
#define GRID 1024             // 2 halves * 2 tiles each = 4 tiles per block
#define C4FULL (CC / 4)       // 64 float4 per full row

// Least-squares constants for t = 0..511:
//   sum_t = 130816, sum_t2 = 44608256, denom = sum_t2 - sum_t^2/n = 11184768
#define SUM_T     130816.0f
#define K1        255.5f
#define INV_DENOM (1.0f / 11184768.0f)
#define INV_N     (1.0f / 512.0f)

__device__ __forceinline__ void f4add(float4& a, const float4 b) {
    a.x += b.x; a.y += b.y; a.z += b.z; a.w += b.w;
}

__global__ __launch_bounds__(NTH)
void lr_forecast_r13(const float* __restrict__ x,
                     float* __restrict__ out,
                     int t_out_len)
{
    const int g    = blockIdx.x;
    const int tid  = threadIdx.x;
    const int h    = tid >> 7;          // half 0 / 1
    const int ht   = tid & (HTH - 1);   // tid within half
    const int c4   = ht & (C4S - 1);    // 0..7  float4 column
    const int lg   = ht >> 3;           // 0..15 l-stride group

    // double-buffered per-half scratch: [half][parity][...]
    __shared__ float4 s_sy [2][2][LGR][C4S];
    __shared__ float4 s_sty[2][2][LGR][C4S];
    __shared__ float4 s_sl[2][2][C4S];
    __shared__ float4 s_ic[2][2][C4S];

    const int barid = h + 1;   // named barriers 1 and 2 (never bar 0)
    auto half_bar = [&]() {
        asm volatile("bar.sync %0, %1;" :: "r"(barid), "r"(HTH) : "memory");
    };

    // ---- monolithic read phase (front-batched 8-deep LDG.128) ----
    auto read_tile = [&](int tile, int pb, float4& sl_o, float4& ic_o) {
        const int b  = tile >> 3;
        const int cs = tile & (CSL - 1);
        const float4* xb = reinterpret_cast<const float4*>(
                               x + (size_t)b * LL * CC) + cs * C4S + c4;
        float4 sy  = make_float4(0.f, 0.f, 0.f, 0.f);
        float4 sty = make_float4(0.f, 0.f, 0.f, 0.f);
        #pragma unroll 8
        for (int i = 0; i < RITER; i++) {
            int l = lg + i * LGR;
            float4 v = __ldg(&xb[(size_t)l * C4FULL]);
            float tf = (float)l;
            f4add(sy, v);
            sty.x = fmaf(tf, v.x, sty.x);
            sty.y = fmaf(tf, v.y, sty.y);
            sty.z = fmaf(tf, v.z, sty.z);
            sty.w = fmaf(tf, v.w, sty.w);
        }
        // smem tree reduce over 16 l-groups within this half (parity buffer pb)
        s_sy [h][pb][lg][c4] = sy;
        s_sty[h][pb][lg][c4] = sty;
        half_bar();
        if (lg < 4) {
            float4 a = s_sy[h][pb][lg][c4];
            f4add(a, s_sy[h][pb][lg +  4][c4]);
            f4add(a, s_sy[h][pb][lg +  8][c4]);
            f4add(a, s_sy[h][pb][lg + 12][c4]);
            s_sy[h][pb][lg][c4] = a;
            float4 t = s_sty[h][pb][lg][c4];
            f4add(t, s_sty[h][pb][lg +  4][c4]);
            f4add(t, s_sty[h][pb][lg +  8][c4]);
            f4add(t, s_sty[h][pb][lg + 12][c4]);
            s_sty[h][pb][lg][c4] = t;
        }
        half_bar();
        if (lg == 0) {
            float4 Sy = s_sy[h][pb][0][c4], Sty = s_sty[h][pb][0][c4];
            f4add(Sy,  s_sy [h][pb][1][c4]);
            f4add(Sy,  s_sy [h][pb][2][c4]);
            f4add(Sy,  s_sy [h][pb][3][c4]);
            f4add(Sty, s_sty[h][pb][1][c4]);
            f4add(Sty, s_sty[h][pb][2][c4]);
            f4add(Sty, s_sty[h][pb][3][c4]);
            float4 SL, IC;
            SL.x = (Sty.x - K1 * Sy.x) * INV_DENOM;
            SL.y = (Sty.y - K1 * Sy.y) * INV_DENOM;
            SL.z = (Sty.z - K1 * Sy.z) * INV_DENOM;
            SL.w = (Sty.w - K1 * Sy.w) * INV_DENOM;
            IC.x = (Sy.x - SL.x * SUM_T) * INV_N;
            IC.y = (Sy.y - SL.y * SUM_T) * INV_N;
            IC.z = (Sy.z - SL.z * SUM_T) * INV_N;
            IC.w = (Sy.w - SL.w * SUM_T) * INV_N;
            s_sl[h][pb][c4] = SL;
            s_ic[h][pb][c4] = IC;
        }
        half_bar();
        sl_o = s_sl[h][pb][c4];
        ic_o = s_ic[h][pb][c4];
        // no trailing barrier: the next read_tile uses the other parity buffer
    };

    // ---- monolithic write phase (streaming stores, evict-first) ----
    auto write_tile = [&](int tile, float4 sl, float4 ic) {
        const int b  = tile >> 3;
        const int cs = tile & (CSL - 1);
        float4* ob = reinterpret_cast<float4*>(
                         out + (size_t)b * t_out_len * CC) + cs * C4S + c4;
        #pragma unroll 8
        for (int t = lg; t < t_out_len; t += LGR) {   // 38 iters
            float tf = (float)t;
            float4 o;
            o.x = fmaf(sl.x, tf, ic.x);
            o.y = fmaf(sl.y, tf, ic.y);
            o.z = fmaf(sl.z, tf, ic.z);
            o.w = fmaf(sl.w, tf, ic.w);
            __stcs(&ob[(size_t)t * C4FULL], o);
        }
    };

    // tiles for this half: T0 = g + (2h)*GRID, T1 = g + (2h+1)*GRID
    const int t0 = g + (2 * h) * GRID;
    const int t1 = g + (2 * h + 1) * GRID;

    float4 sl0, ic0, sl1, ic1;

    if (h == 0) {
        // Half 0: R0 W0 R1 W1
        read_tile(t0, 0, sl0, ic0);
        write_tile(t0, sl0, ic0);
        read_tile(t1, 1, sl1, ic1);
        write_tile(t1, sl1, ic1);
    } else {
        // Half 1 (depth-2 pipeline): R0 R1 W0 W1
        // -> while half 0 writes, half 1 reads, and vice versa.
        read_tile(t0, 0, sl0, ic0);
        read_tile(t1, 1, sl1, ic1);
        write_tile(t0, sl0, ic0);
        write_tile(t1, sl1, ic1);
    }
}

extern "C" void kernel_launch(void* const* d_in, const int* in_sizes, int n_in,
                              void* d_out, int out_size)
{
    const float* x = (const float*)d_in[0];
    float* out = (float*)d_out;
    int t_out_len = out_size / (BB * CC);   // 608 for pred_len = 96

    lr_forecast_r13<<<GRID, NTH>>>(x, out, t_out_len);
}